// round 11
// baseline (speedup 1.0000x reference)
#include <cuda_runtime.h>
#include <math_constants.h>

#define NB 8
#define NP 4096
#define THREADS 256
#define ILX 8                        // scalar x-points per thread (duplicated-packed)
#define XCHUNK (THREADS * ILX)       // 2048
#define XC (NP / XCHUNK)             // 2
#define YT 256
#define YP (YT / 2)                  // 128 j-pairs
#define YC (NP / YT)                 // 16
#define NDB (2 * NB)                 // 16 (dir, batch) pairs
#define RBLOCKS 64

#define FMA_F32X2(d, a, b, c) \
    asm("fma.rn.f32x2 %0, %1, %2, %3;" : "=l"(d) : "l"(a), "l"(b), "l"(c))
#define PACK_F32X2(out, lo, hi) \
    asm("mov.b64 %0, {%1, %2};" : "=l"(out) : "f"(lo), "f"(hi))
#define UNPACK_F32X2(lo, hi, in) \
    asm("mov.b64 {%0, %1}, %2;" : "=f"(lo), "=f"(hi) : "l"(in))

// Per-(dir,batch,y-tile) partial mins. Plain stores, no init, no atomics.
__device__ float g_part[NDB * YC * NP];
__device__ float g_psum[RBLOCKS];

__global__ __launch_bounds__(THREADS, 2) void chamfer_kernel(
    const float* __restrict__ x, const float* __restrict__ y) {
    // Two y-points per entry; one LDS.128 yields two packed f32x2 operands:
    //   sA[jp] = {nx_j0, nx_j1, ny_j0, ny_j1}
    //   sB[jp] = {nz_j0, nz_j1, pp_j0, pp_j1}
    // Padded by 1 entry for depth-1 prefetch overrun.
    __shared__ float4 sA[YP + 1], sB[YP + 1];

    const int yc   = blockIdx.x;
    const int xc   = blockIdx.y;
    const int dirb = blockIdx.z;
    const int dir  = dirb >> 3;
    const int b    = dirb & 7;

    const float* A  = dir ? y : x;
    const float* P  = dir ? x : y;
    const float* Ab = A + b * 3 * NP;
    const float* Pb = P + b * 3 * NP;

    const int tid = threadIdx.x;

    // Stage y-tile (YP=128 entries; first 128 threads).
    if (tid < YP) {
        int jp = tid;
        int g0 = yc * YT + 2 * jp;
        int g1 = g0 + 1;
        float px0 = Pb[g0],          px1 = Pb[g1];
        float py0 = Pb[NP + g0],     py1 = Pb[NP + g1];
        float pz0 = Pb[2 * NP + g0], pz1 = Pb[2 * NP + g1];
        float pp0 = fmaf(pz0, pz0, fmaf(py0, py0, px0 * px0));
        float pp1 = fmaf(pz1, pz1, fmaf(py1, py1, px1 * px1));
        sA[jp] = make_float4(-2.0f * px0, -2.0f * px1, -2.0f * py0, -2.0f * py1);
        sB[jp] = make_float4(-2.0f * pz0, -2.0f * pz1, pp0, pp1);
    }
    if (tid == 0) {  // init pad (prefetched but never used in a min)
        sA[YP] = make_float4(0.f, 0.f, 0.f, 0.f);
        sB[YP] = make_float4(0.f, 0.f, 0.f, 0.f);
    }
    __syncthreads();

    // Duplicated-packed x operands (loop invariant). 8 independent chains.
    unsigned long long axd[ILX], ayd[ILX], azd[ILX];
    float aa[ILX], mn[ILX];
#pragma unroll
    for (int k = 0; k < ILX; k++) {
        int gi = xc * XCHUNK + k * THREADS + tid;
        float ax = Ab[gi], ay = Ab[NP + gi], az = Ab[2 * NP + gi];
        PACK_F32X2(axd[k], ax, ax);
        PACK_F32X2(ayd[k], ay, ay);
        PACK_F32X2(azd[k], az, az);
        aa[k] = fmaf(az, az, fmaf(ay, ay, ax * ax));
        mn[k] = CUDART_INF_F;
    }

    // Depth-1 software pipeline: prefetch next jp while computing current.
    ulonglong2 va = *reinterpret_cast<const ulonglong2*>(&sA[0]);
    ulonglong2 vb = *reinterpret_cast<const ulonglong2*>(&sB[0]);
#pragma unroll 2
    for (int jp = 0; jp < YP; jp++) {
        ulonglong2 nva = *reinterpret_cast<const ulonglong2*>(&sA[jp + 1]);
        ulonglong2 nvb = *reinterpret_cast<const ulonglong2*>(&sB[jp + 1]);
        const unsigned long long mx = va.x;  // {nx0, nx1}
        const unsigned long long my = va.y;  // {ny0, ny1}
        const unsigned long long mz = vb.x;  // {nz0, nz1}
        const unsigned long long pp = vb.y;  // {pp0, pp1}
#pragma unroll
        for (int k = 0; k < ILX; k++) {
            unsigned long long t;
            FMA_F32X2(t, axd[k], mx, pp);
            FMA_F32X2(t, ayd[k], my, t);
            FMA_F32X2(t, azd[k], mz, t);
            float lo, hi;
            UNPACK_F32X2(lo, hi, t);
            mn[k] = fminf(mn[k], fminf(lo, hi));  // short carried chain
        }
        va = nva;
        vb = nvb;
    }

    float* gp = g_part + (dirb * YC + yc) * NP;
#pragma unroll
    for (int k = 0; k < ILX; k++) {
        int gi = xc * XCHUNK + k * THREADS + tid;
        gp[gi] = aa[k] + mn[k];
    }
}

// Stage A: min over the YC partial tiles, accumulate per-block sums.
__global__ __launch_bounds__(256) void reduceA_kernel() {
    __shared__ float sred[256];
    const int tid = threadIdx.x;
    float s = 0.0f;
#pragma unroll
    for (int k = 0; k < 4; k++) {
        int pt = blockIdx.x * 1024 + k * 256 + tid;  // global point 0..65535
        int db = pt >> 12;
        int p  = pt & (NP - 1);
        const float* gp = g_part + db * YC * NP + p;
        float m = gp[0];
#pragma unroll
        for (int yc = 1; yc < YC; yc++) m = fminf(m, gp[yc * NP]);
        s += m;
    }
    sred[tid] = s;
    __syncthreads();
    for (int w = 128; w > 0; w >>= 1) {
        if (tid < w) sred[tid] += sred[tid + w];
        __syncthreads();
    }
    if (tid == 0) g_psum[blockIdx.x] = sred[0];
}

// Stage B: final scalar.
__global__ void reduceB_kernel(float* __restrict__ out) {
    __shared__ float sred[RBLOCKS];
    int tid = threadIdx.x;
    sred[tid] = g_psum[tid];
    __syncthreads();
    for (int w = RBLOCKS / 2; w > 0; w >>= 1) {
        if (tid < w) sred[tid] += sred[tid + w];
        __syncthreads();
    }
    if (tid == 0) out[0] = sred[0] / (float)(NB * NP);
}

extern "C" void kernel_launch(void* const* d_in, const int* in_sizes, int n_in,
                              void* d_out, int out_size) {
    const float* x = (const float*)d_in[0];
    const float* y = (const float*)d_in[1];
    float* out = (float*)d_out;

    dim3 grid(YC, XC, NDB);  // 16 x 2 x 16 = 512 blocks
    chamfer_kernel<<<grid, THREADS>>>(x, y);
    reduceA_kernel<<<RBLOCKS, 256>>>();
    reduceB_kernel<<<1, RBLOCKS>>>(out);
}

// round 12
// speedup vs baseline: 1.0506x; 1.0506x over previous
#include <cuda_runtime.h>
#include <math_constants.h>

#define NB 8
#define NP 4096
#define THREADS 256
#define ILX 4                        // scalar x-points per thread (duplicated-packed)
#define XCHUNK (THREADS * ILX)       // 1024
#define XC (NP / XCHUNK)             // 4
#define YT 256
#define YP (YT / 2)                  // 128 j-pairs
#define YC (NP / YT)                 // 16
#define NDB (2 * NB)                 // 16 (dir, batch) pairs
#define RBLOCKS 256

#define FMA_F32X2(d, a, b, c) \
    asm("fma.rn.f32x2 %0, %1, %2, %3;" : "=l"(d) : "l"(a), "l"(b), "l"(c))
#define PACK_F32X2(out, lo, hi) \
    asm("mov.b64 %0, {%1, %2};" : "=l"(out) : "f"(lo), "f"(hi))
#define UNPACK_F32X2(lo, hi, in) \
    asm("mov.b64 {%0, %1}, %2;" : "=f"(lo), "=f"(hi) : "l"(in))

// Per-(dir,batch,y-tile) partial mins. Plain stores, no init, no atomics.
__device__ float g_part[NDB * YC * NP];
__device__ float g_psum[RBLOCKS];

__global__ __launch_bounds__(THREADS, 3) void chamfer_kernel(
    const float* __restrict__ x, const float* __restrict__ y) {
    // Two y-points per entry; one LDS.128 yields two packed f32x2 operands:
    //   sA[jp] = {nx_j0, nx_j1, ny_j0, ny_j1}
    //   sB[jp] = {nz_j0, nz_j1, pp_j0, pp_j1}
    // Padded by 1 entry for depth-1 prefetch overrun.
    __shared__ float4 sA[YP + 1], sB[YP + 1];

    const int yc   = blockIdx.x;
    const int xc   = blockIdx.y;
    const int dirb = blockIdx.z;
    const int dir  = dirb >> 3;
    const int b    = dirb & 7;

    const float* A  = dir ? y : x;
    const float* P  = dir ? x : y;
    const float* Ab = A + b * 3 * NP;
    const float* Pb = P + b * 3 * NP;

    const int tid = threadIdx.x;

    // Stage y-tile (YP=128 entries; first 128 threads).
    if (tid < YP) {
        int jp = tid;
        int g0 = yc * YT + 2 * jp;
        int g1 = g0 + 1;
        float px0 = Pb[g0],          px1 = Pb[g1];
        float py0 = Pb[NP + g0],     py1 = Pb[NP + g1];
        float pz0 = Pb[2 * NP + g0], pz1 = Pb[2 * NP + g1];
        float pp0 = fmaf(pz0, pz0, fmaf(py0, py0, px0 * px0));
        float pp1 = fmaf(pz1, pz1, fmaf(py1, py1, px1 * px1));
        sA[jp] = make_float4(-2.0f * px0, -2.0f * px1, -2.0f * py0, -2.0f * py1);
        sB[jp] = make_float4(-2.0f * pz0, -2.0f * pz1, pp0, pp1);
    }
    if (tid == 0) {  // init pad (prefetched but never used in a min)
        sA[YP] = make_float4(0.f, 0.f, 0.f, 0.f);
        sB[YP] = make_float4(0.f, 0.f, 0.f, 0.f);
    }
    __syncthreads();

    // Duplicated-packed x operands (loop invariant). 4 independent chains.
    unsigned long long axd[ILX], ayd[ILX], azd[ILX];
    float aa[ILX], mn[ILX];
#pragma unroll
    for (int k = 0; k < ILX; k++) {
        int gi = xc * XCHUNK + k * THREADS + tid;
        float ax = Ab[gi], ay = Ab[NP + gi], az = Ab[2 * NP + gi];
        PACK_F32X2(axd[k], ax, ax);
        PACK_F32X2(ayd[k], ay, ay);
        PACK_F32X2(azd[k], az, az);
        aa[k] = fmaf(az, az, fmaf(ay, ay, ax * ax));
        mn[k] = CUDART_INF_F;
    }

    // Depth-1 software pipeline: prefetch next jp while computing current.
    ulonglong2 va = *reinterpret_cast<const ulonglong2*>(&sA[0]);
    ulonglong2 vb = *reinterpret_cast<const ulonglong2*>(&sB[0]);
#pragma unroll 4
    for (int jp = 0; jp < YP; jp++) {
        ulonglong2 nva = *reinterpret_cast<const ulonglong2*>(&sA[jp + 1]);
        ulonglong2 nvb = *reinterpret_cast<const ulonglong2*>(&sB[jp + 1]);
        const unsigned long long mx = va.x;  // {nx0, nx1}
        const unsigned long long my = va.y;  // {ny0, ny1}
        const unsigned long long mz = vb.x;  // {nz0, nz1}
        const unsigned long long pp = vb.y;  // {pp0, pp1}
#pragma unroll
        for (int k = 0; k < ILX; k++) {
            unsigned long long t;
            FMA_F32X2(t, axd[k], mx, pp);
            FMA_F32X2(t, ayd[k], my, t);
            FMA_F32X2(t, azd[k], mz, t);
            float lo, hi;
            UNPACK_F32X2(lo, hi, t);
            mn[k] = fminf(mn[k], fminf(lo, hi));  // short carried chain
        }
        va = nva;
        vb = nvb;
    }

    float* gp = g_part + (dirb * YC + yc) * NP;
#pragma unroll
    for (int k = 0; k < ILX; k++) {
        int gi = xc * XCHUNK + k * THREADS + tid;
        gp[gi] = aa[k] + mn[k];
    }
}

// Stage A: one point per thread; min over YC partial tiles (16 independent
// L2-resident loads, MLP=16), then block tree-sum. 256 blocks.
__global__ __launch_bounds__(256) void reduceA_kernel() {
    __shared__ float sred[256];
    const int tid = threadIdx.x;
    const int pt  = blockIdx.x * 256 + tid;  // global point 0..65535
    const int db  = pt >> 12;
    const int p   = pt & (NP - 1);
    const float* gp = g_part + db * YC * NP + p;

    float v[YC];
#pragma unroll
    for (int yc = 0; yc < YC; yc++) v[yc] = gp[yc * NP];
    float m = v[0];
#pragma unroll
    for (int yc = 1; yc < YC; yc++) m = fminf(m, v[yc]);

    sred[tid] = m;
    __syncthreads();
    for (int w = 128; w > 0; w >>= 1) {
        if (tid < w) sred[tid] += sred[tid + w];
        __syncthreads();
    }
    if (tid == 0) g_psum[blockIdx.x] = sred[0];
}

// Stage B: final scalar.
__global__ __launch_bounds__(RBLOCKS) void reduceB_kernel(float* __restrict__ out) {
    __shared__ float sred[RBLOCKS];
    int tid = threadIdx.x;
    sred[tid] = g_psum[tid];
    __syncthreads();
    for (int w = RBLOCKS / 2; w > 0; w >>= 1) {
        if (tid < w) sred[tid] += sred[tid + w];
        __syncthreads();
    }
    if (tid == 0) out[0] = sred[0] / (float)(NB * NP);
}

extern "C" void kernel_launch(void* const* d_in, const int* in_sizes, int n_in,
                              void* d_out, int out_size) {
    const float* x = (const float*)d_in[0];
    const float* y = (const float*)d_in[1];
    float* out = (float*)d_out;

    dim3 grid(YC, XC, NDB);  // 16 x 4 x 16 = 1024 blocks
    chamfer_kernel<<<grid, THREADS>>>(x, y);
    reduceA_kernel<<<RBLOCKS, 256>>>();
    reduceB_kernel<<<1, RBLOCKS>>>(out);
}

// round 13
// speedup vs baseline: 1.1211x; 1.0671x over previous
#include <cuda_runtime.h>
#include <math_constants.h>

#define NB 8
#define NP 4096
#define THREADS 256
#define ILX 4                        // scalar x-points per thread (duplicated-packed)
#define XCHUNK (THREADS * ILX)       // 1024
#define XC (NP / XCHUNK)             // 4
#define YT 256
#define YP (YT / 2)                  // 128 j-pairs
#define YC (NP / YT)                 // 16
#define NDB (2 * NB)                 // 16 (dir, batch) pairs
#define RBLOCKS 256

#define FMA_F32X2(d, a, b, c) \
    asm("fma.rn.f32x2 %0, %1, %2, %3;" : "=l"(d) : "l"(a), "l"(b), "l"(c))
#define PACK_F32X2(out, lo, hi) \
    asm("mov.b64 %0, {%1, %2};" : "=l"(out) : "f"(lo), "f"(hi))
#define UNPACK_F32X2(lo, hi, in) \
    asm("mov.b64 {%0, %1}, %2;" : "=f"(lo), "=f"(hi) : "l"(in))

// Per-(dir,batch,y-tile) partial mins. Plain stores, no init, no atomics.
__device__ float g_part[NDB * YC * NP];
__device__ float g_psum[RBLOCKS];
__device__ int   g_count;  // zero-initialized; last block resets to 0 each launch

__global__ __launch_bounds__(THREADS, 3) void chamfer_kernel(
    const float* __restrict__ x, const float* __restrict__ y) {
    // Two y-points per entry; one LDS.128 yields two packed f32x2 operands:
    //   sA[jp] = {nx_j0, nx_j1, ny_j0, ny_j1}
    //   sB[jp] = {nz_j0, nz_j1, pp_j0, pp_j1}
    // Padded by 1 entry for depth-1 prefetch overrun.
    __shared__ float4 sA[YP + 1], sB[YP + 1];

    const int yc   = blockIdx.x;
    const int xc   = blockIdx.y;
    const int dirb = blockIdx.z;
    const int dir  = dirb >> 3;
    const int b    = dirb & 7;

    const float* A  = dir ? y : x;
    const float* P  = dir ? x : y;
    const float* Ab = A + b * 3 * NP;
    const float* Pb = P + b * 3 * NP;

    const int tid = threadIdx.x;

    // Stage y-tile (YP=128 entries; first 128 threads).
    if (tid < YP) {
        int jp = tid;
        int g0 = yc * YT + 2 * jp;
        int g1 = g0 + 1;
        float px0 = Pb[g0],          px1 = Pb[g1];
        float py0 = Pb[NP + g0],     py1 = Pb[NP + g1];
        float pz0 = Pb[2 * NP + g0], pz1 = Pb[2 * NP + g1];
        float pp0 = fmaf(pz0, pz0, fmaf(py0, py0, px0 * px0));
        float pp1 = fmaf(pz1, pz1, fmaf(py1, py1, px1 * px1));
        sA[jp] = make_float4(-2.0f * px0, -2.0f * px1, -2.0f * py0, -2.0f * py1);
        sB[jp] = make_float4(-2.0f * pz0, -2.0f * pz1, pp0, pp1);
    }
    if (tid == 0) {  // init pad (prefetched but never used in a min)
        sA[YP] = make_float4(0.f, 0.f, 0.f, 0.f);
        sB[YP] = make_float4(0.f, 0.f, 0.f, 0.f);
    }
    __syncthreads();

    // Duplicated-packed x operands (loop invariant). 4 independent chains.
    unsigned long long axd[ILX], ayd[ILX], azd[ILX];
    float aa[ILX], mn[ILX];
#pragma unroll
    for (int k = 0; k < ILX; k++) {
        int gi = xc * XCHUNK + k * THREADS + tid;
        float ax = Ab[gi], ay = Ab[NP + gi], az = Ab[2 * NP + gi];
        PACK_F32X2(axd[k], ax, ax);
        PACK_F32X2(ayd[k], ay, ay);
        PACK_F32X2(azd[k], az, az);
        aa[k] = fmaf(az, az, fmaf(ay, ay, ax * ax));
        mn[k] = CUDART_INF_F;
    }

    // Depth-1 software pipeline: prefetch next jp while computing current.
    ulonglong2 va = *reinterpret_cast<const ulonglong2*>(&sA[0]);
    ulonglong2 vb = *reinterpret_cast<const ulonglong2*>(&sB[0]);
#pragma unroll 8
    for (int jp = 0; jp < YP; jp++) {
        ulonglong2 nva = *reinterpret_cast<const ulonglong2*>(&sA[jp + 1]);
        ulonglong2 nvb = *reinterpret_cast<const ulonglong2*>(&sB[jp + 1]);
        const unsigned long long mx = va.x;  // {nx0, nx1}
        const unsigned long long my = va.y;  // {ny0, ny1}
        const unsigned long long mz = vb.x;  // {nz0, nz1}
        const unsigned long long pp = vb.y;  // {pp0, pp1}
#pragma unroll
        for (int k = 0; k < ILX; k++) {
            unsigned long long t;
            FMA_F32X2(t, axd[k], mx, pp);
            FMA_F32X2(t, ayd[k], my, t);
            FMA_F32X2(t, azd[k], mz, t);
            float lo, hi;
            UNPACK_F32X2(lo, hi, t);
            mn[k] = fminf(mn[k], fminf(lo, hi));  // short carried chain
        }
        va = nva;
        vb = nvb;
    }

    float* gp = g_part + (dirb * YC + yc) * NP;
#pragma unroll
    for (int k = 0; k < ILX; k++) {
        int gi = xc * XCHUNK + k * THREADS + tid;
        gp[gi] = aa[k] + mn[k];
    }
}

// Fused reduce: per-point min over YC tiles + block sum; last-done block
// folds the 256 partials and writes the scalar, then resets the counter
// (graph-replay safe, deterministic).
__global__ __launch_bounds__(256) void reduce_kernel(float* __restrict__ out) {
    __shared__ float sred[256];
    __shared__ int s_last;
    const int tid = threadIdx.x;
    const int pt  = blockIdx.x * 256 + tid;  // global point 0..65535
    const int db  = pt >> 12;
    const int p   = pt & (NP - 1);
    const float* gp = g_part + db * YC * NP + p;

    float v[YC];
#pragma unroll
    for (int yc = 0; yc < YC; yc++) v[yc] = gp[yc * NP];
    float m = v[0];
#pragma unroll
    for (int yc = 1; yc < YC; yc++) m = fminf(m, v[yc]);

    sred[tid] = m;
    __syncthreads();
    for (int w = 128; w > 0; w >>= 1) {
        if (tid < w) sred[tid] += sred[tid + w];
        __syncthreads();
    }
    if (tid == 0) {
        g_psum[blockIdx.x] = sred[0];
        __threadfence();
        int prev = atomicAdd(&g_count, 1);
        s_last = (prev == gridDim.x - 1) ? 1 : 0;
    }
    __syncthreads();

    if (s_last) {
        float s = g_psum[tid];
        sred[tid] = s;
        __syncthreads();
        for (int w = 128; w > 0; w >>= 1) {
            if (tid < w) sred[tid] += sred[tid + w];
            __syncthreads();
        }
        if (tid == 0) {
            out[0] = sred[0] / (float)(NB * NP);
            g_count = 0;  // reset for next graph replay
        }
    }
}

extern "C" void kernel_launch(void* const* d_in, const int* in_sizes, int n_in,
                              void* d_out, int out_size) {
    const float* x = (const float*)d_in[0];
    const float* y = (const float*)d_in[1];
    float* out = (float*)d_out;

    dim3 grid(YC, XC, NDB);  // 16 x 4 x 16 = 1024 blocks
    chamfer_kernel<<<grid, THREADS>>>(x, y);
    reduce_kernel<<<RBLOCKS, 256>>>(out);
}

// round 14
// speedup vs baseline: 1.1316x; 1.0093x over previous
#include <cuda_runtime.h>
#include <math_constants.h>

#define NB 8
#define NP 4096
#define THREADS 256
#define ILX 4                        // scalar x-points per thread (duplicated-packed)
#define XCHUNK (THREADS * ILX)       // 1024
#define XC (NP / XCHUNK)             // 4
#define YT 256
#define YP (YT / 2)                  // 128 j-pairs
#define YC (NP / YT)                 // 16
#define NDB (2 * NB)                 // 16 (dir, batch) pairs
#define RBLOCKS 64                   // reduce: 64 blocks x 256 thr x 4 vals

#define FMA_F32X2(d, a, b, c) \
    asm("fma.rn.f32x2 %0, %1, %2, %3;" : "=l"(d) : "l"(a), "l"(b), "l"(c))
#define PACK_F32X2(out, lo, hi) \
    asm("mov.b64 %0, {%1, %2};" : "=l"(out) : "f"(lo), "f"(hi))
#define UNPACK_F32X2(lo, hi, in) \
    asm("mov.b64 {%0, %1}, %2;" : "=f"(lo), "=f"(hi) : "l"(in))

// Per-(dir,batch,point) running min, as a transformed unsigned key where
// LARGER unsigned == SMALLER float, and 0 == "+inf". So atomicMax implements
// float-min and BSS zero-init is the correct initial state. The reduce
// kernel resets slots to 0 after consuming them -> every graph replay sees
// the same initial state (deterministic, no init kernel).
__device__ unsigned int g_min[NDB * NP];    // 256 KB
__device__ float g_psum[RBLOCKS];
__device__ int   g_count;                   // reset to 0 by last reduce block

__device__ __forceinline__ unsigned int min_key(float f) {
    int i = __float_as_int(f);
    i = i < 0 ? (i ^ 0x7FFFFFFF) : i;                 // total order as signed int
    return ~((unsigned int)i ^ 0x80000000u);          // flip to unsigned, invert
}
__device__ __forceinline__ float min_key_inv(unsigned int s) {
    int i = (int)(~s ^ 0x80000000u);
    i = i < 0 ? (i ^ 0x7FFFFFFF) : i;
    return __int_as_float(i);
}

__global__ __launch_bounds__(THREADS, 3) void chamfer_kernel(
    const float* __restrict__ x, const float* __restrict__ y) {
    // Two y-points per entry; one LDS.128 yields two packed f32x2 operands:
    //   sA[jp] = {nx_j0, nx_j1, ny_j0, ny_j1}
    //   sB[jp] = {nz_j0, nz_j1, pp_j0, pp_j1}
    // Padded by 1 entry for depth-1 prefetch overrun.
    __shared__ float4 sA[YP + 1], sB[YP + 1];

    const int yc   = blockIdx.x;
    const int xc   = blockIdx.y;
    const int dirb = blockIdx.z;
    const int dir  = dirb >> 3;
    const int b    = dirb & 7;

    const float* A  = dir ? y : x;
    const float* P  = dir ? x : y;
    const float* Ab = A + b * 3 * NP;
    const float* Pb = P + b * 3 * NP;

    const int tid = threadIdx.x;

    // Stage y-tile (YP=128 entries; first 128 threads).
    if (tid < YP) {
        int jp = tid;
        int g0 = yc * YT + 2 * jp;
        int g1 = g0 + 1;
        float px0 = Pb[g0],          px1 = Pb[g1];
        float py0 = Pb[NP + g0],     py1 = Pb[NP + g1];
        float pz0 = Pb[2 * NP + g0], pz1 = Pb[2 * NP + g1];
        float pp0 = fmaf(pz0, pz0, fmaf(py0, py0, px0 * px0));
        float pp1 = fmaf(pz1, pz1, fmaf(py1, py1, px1 * px1));
        sA[jp] = make_float4(-2.0f * px0, -2.0f * px1, -2.0f * py0, -2.0f * py1);
        sB[jp] = make_float4(-2.0f * pz0, -2.0f * pz1, pp0, pp1);
    }
    if (tid == 0) {  // init pad (prefetched but never used in a min)
        sA[YP] = make_float4(0.f, 0.f, 0.f, 0.f);
        sB[YP] = make_float4(0.f, 0.f, 0.f, 0.f);
    }
    __syncthreads();

    // Duplicated-packed x operands (loop invariant). 4 independent chains.
    unsigned long long axd[ILX], ayd[ILX], azd[ILX];
    float aa[ILX], mn[ILX];
#pragma unroll
    for (int k = 0; k < ILX; k++) {
        int gi = xc * XCHUNK + k * THREADS + tid;
        float ax = Ab[gi], ay = Ab[NP + gi], az = Ab[2 * NP + gi];
        PACK_F32X2(axd[k], ax, ax);
        PACK_F32X2(ayd[k], ay, ay);
        PACK_F32X2(azd[k], az, az);
        aa[k] = fmaf(az, az, fmaf(ay, ay, ax * ax));
        mn[k] = CUDART_INF_F;
    }

    // Depth-1 software pipeline: prefetch next jp while computing current.
    ulonglong2 va = *reinterpret_cast<const ulonglong2*>(&sA[0]);
    ulonglong2 vb = *reinterpret_cast<const ulonglong2*>(&sB[0]);
#pragma unroll 8
    for (int jp = 0; jp < YP; jp++) {
        ulonglong2 nva = *reinterpret_cast<const ulonglong2*>(&sA[jp + 1]);
        ulonglong2 nvb = *reinterpret_cast<const ulonglong2*>(&sB[jp + 1]);
        const unsigned long long mx = va.x;  // {nx0, nx1}
        const unsigned long long my = va.y;  // {ny0, ny1}
        const unsigned long long mz = vb.x;  // {nz0, nz1}
        const unsigned long long pp = vb.y;  // {pp0, pp1}
#pragma unroll
        for (int k = 0; k < ILX; k++) {
            unsigned long long t;
            FMA_F32X2(t, axd[k], mx, pp);
            FMA_F32X2(t, ayd[k], my, t);
            FMA_F32X2(t, azd[k], mz, t);
            float lo, hi;
            UNPACK_F32X2(lo, hi, t);
            mn[k] = fminf(mn[k], fminf(lo, hi));  // short carried chain
        }
        va = nva;
        vb = nvb;
    }

    unsigned int* gm = g_min + dirb * NP;
#pragma unroll
    for (int k = 0; k < ILX; k++) {
        int gi = xc * XCHUNK + k * THREADS + tid;
        atomicMax(&gm[gi], min_key(aa[k] + mn[k]));  // RED.MAX, float-min
    }
}

// Fused reduce: decode + sum 64K keys (coalesced uint4), reset slots to 0
// for the next replay; last-done block folds partials and writes the scalar.
__global__ __launch_bounds__(256) void reduce_kernel(float* __restrict__ out) {
    __shared__ float sred[256];
    __shared__ int s_last;
    const int tid = threadIdx.x;
    const int base = (blockIdx.x * 256 + tid) * 4;  // 4 consecutive keys

    uint4 v = *reinterpret_cast<const uint4*>(&g_min[base]);
    *reinterpret_cast<uint4*>(&g_min[base]) = make_uint4(0u, 0u, 0u, 0u);

    float s = min_key_inv(v.x) + min_key_inv(v.y) +
              min_key_inv(v.z) + min_key_inv(v.w);

    sred[tid] = s;
    __syncthreads();
    for (int w = 128; w > 0; w >>= 1) {
        if (tid < w) sred[tid] += sred[tid + w];
        __syncthreads();
    }
    if (tid == 0) {
        g_psum[blockIdx.x] = sred[0];
        __threadfence();
        int prev = atomicAdd(&g_count, 1);
        s_last = (prev == gridDim.x - 1) ? 1 : 0;
    }
    __syncthreads();

    if (s_last) {
        float t = (tid < RBLOCKS) ? g_psum[tid] : 0.0f;
        sred[tid] = t;
        __syncthreads();
        for (int w = 128; w > 0; w >>= 1) {
            if (tid < w) sred[tid] += sred[tid + w];
            __syncthreads();
        }
        if (tid == 0) {
            out[0] = sred[0] / (float)(NB * NP);
            g_count = 0;  // reset for next graph replay
        }
    }
}

extern "C" void kernel_launch(void* const* d_in, const int* in_sizes, int n_in,
                              void* d_out, int out_size) {
    const float* x = (const float*)d_in[0];
    const float* y = (const float*)d_in[1];
    float* out = (float*)d_out;

    dim3 grid(YC, XC, NDB);  // 16 x 4 x 16 = 1024 blocks
    chamfer_kernel<<<grid, THREADS>>>(x, y);
    reduce_kernel<<<RBLOCKS, 256>>>(out);
}